// round 13
// baseline (speedup 1.0000x reference)
#include <cuda_runtime.h>

#define THREADS 128
#define RPC 8          // rows per CTA
#define XS 132         // x / qk row stride (floats), mult of 4, not mult of 32

// shared memory layout (float offsets) — x double-buffered, W read from gmem
#define OFF_X0  0
#define OFF_X1  (OFF_X0 + 32*XS)
#define OFF_QK  (OFF_X1 + 32*XS)
#define OFF_B   (OFF_QK + 32*XS)
#define OFF_WR0 (OFF_B + 128)
#define OFF_WR1 (OFF_WR0 + 32)
#define OFF_CWS (OFF_WR1 + 32)
#define OFF_CS  (OFF_CWS + 128)
#define SMEM_FLOATS (OFF_CS + 32)   // 13024 floats = 52096 B -> 4 CTAs/SM

// ---- packed fp32x2 helpers (sm_10x FFMA2 path, PTX-only) ----
__device__ __forceinline__ unsigned long long ffma2(unsigned long long a,
                                                    unsigned long long b,
                                                    unsigned long long c) {
    unsigned long long d;
    asm("fma.rn.f32x2 %0, %1, %2, %3;" : "=l"(d) : "l"(a), "l"(b), "l"(c));
    return d;
}
__device__ __forceinline__ void unpack2(unsigned long long v, float& lo, float& hi) {
    asm("mov.b64 {%0, %1}, %2;" : "=f"(lo), "=f"(hi) : "l"(v));
}

__global__ __launch_bounds__(THREADS, 4)
void concept_emb_kernel(const int*   __restrict__ g_ids,
                        const float* __restrict__ g_mask,
                        const float* __restrict__ g_times,
                        const float* __restrict__ g_emb,
                        const float* __restrict__ g_qW,
                        const float* __restrict__ g_qb,
                        const float* __restrict__ g_kW,
                        const float* __restrict__ g_kb,
                        const float* __restrict__ g_theta,
                        const float* __restrict__ g_mu,
                        float*       __restrict__ g_out,
                        int n_rows)
{
    extern __shared__ float sm[];
    float* xs0   = sm + OFF_X0;   // [32 n][132] buffer 0
    float* xs1   = sm + OFF_X1;   // [32 n][132] buffer 1
    float* qk    = sm + OFF_QK;   // [32 n][132] : cols 0..63 = q, 64..127 = k
    float* bs    = sm + OFF_B;    // [128] combined bias
    float* wrow0 = sm + OFF_WR0;  // [32] sx * mask, buffer 0
    float* wrow1 = sm + OFF_WR1;  // [32] sx * mask, buffer 1
    float* cws   = sm + OFF_CWS;  // [4 warps][32]
    float* cs    = sm + OFF_CS;   // [32] attention column weights

    const int t    = threadIdx.x;
    const int lane = t & 31;
    const int wid  = t >> 5;

    // phase-2 mapping: warp owns j-quarter [32*wid, 32*wid+32), all 32 n.
    // ng = lane&3 -> interleaved rows {ng, ng+4, ..., ng+28}  (conflict-free LDS)
    // jg = lane>>2 -> 4 consecutive j at jb
    const int ng = lane & 3;
    const int jg = lane >> 2;
    const int jb = 32 * wid + 4 * jg;

    // W source rows: wid 0,1 -> qW rows jb; wid 2,3 -> kW rows jb-64.
    const float* Wsel = (wid < 2) ? g_qW : g_kW;
    const float* wbase = Wsel + (jb & 63) * 128;   // 4 consecutive rows of 128 floats

    bs[t] = (t < 64) ? g_qb[t] : g_kb[t - 64];
    const float4* emb4 = (const float4*)g_emb;

    const int row0 = blockIdx.x * RPC;

    // ---- prologue: gather row0 into buffer 0 ----
    {
        #pragma unroll
        for (int r8 = 0; r8 < 8; ++r8) {
            int n = wid * 8 + r8;
            int id = g_ids[row0 * 32 + n];
            float4 v = emb4[(long)id * 32 + lane];
            *(float4*)&xs0[n * XS + lane * 4] = v;
        }
        if (t < 32) {
            int id = g_ids[row0 * 32 + t];
            float mk = g_mask[row0 * 32 + t];
            float tm = g_times[row0];
            float z  = g_theta[id] - g_mu[id] * tm;
            wrow0[t] = mk / (1.0f + __expf(-z));
        }
    }
    __syncthreads();   // xs0 / wrow0 / bs ready

    // bias for this thread's 4-column j-tile
    const float4 bj = *(const float4*)&bs[jb];

    for (int rr = 0; rr < RPC; ++rr) {
        const int row = row0 + rr;
        const bool active = (row < n_rows);
        float* xcur = (rr & 1) ? xs1 : xs0;
        float* wcur = (rr & 1) ? wrow1 : wrow0;
        float* xnxt = (rr & 1) ? xs0 : xs1;
        float* wnxt = (rr & 1) ? wrow0 : wrow1;

        // ---- phase 2: [q|k] = x @ [qW;kW]^T ----
        // FFMA2 packed along d; 8 W-LDGs batched per 8-d chunk for MLP.
        if (active) {
            unsigned long long acc2[8][4];   // [r][u]: output (row ng+4r, col jb+u)
            #pragma unroll
            for (int r = 0; r < 8; ++r)
                #pragma unroll
                for (int u = 0; u < 4; ++u) acc2[r][u] = 0ULL;

            const float* xp = &xcur[ng * XS];
            #pragma unroll 1
            for (int ds = 0; ds < 16; ++ds) {
                const int d = ds * 8;
                ulonglong2 wv[4][2];
                #pragma unroll
                for (int u = 0; u < 4; ++u) {
                    wv[u][0] = *(const ulonglong2*)(wbase + u * 128 + d);
                    wv[u][1] = *(const ulonglong2*)(wbase + u * 128 + d + 4);
                }
                #pragma unroll
                for (int half = 0; half < 2; ++half) {
                    #pragma unroll
                    for (int rh = 0; rh < 2; ++rh) {
                        ulonglong2 xv[4];
                        #pragma unroll
                        for (int i = 0; i < 4; ++i)
                            xv[i] = *(const ulonglong2*)(xp + (4 * (rh * 4 + i)) * XS
                                                         + d + half * 4);
                        #pragma unroll
                        for (int i = 0; i < 4; ++i) {
                            const int r = rh * 4 + i;
                            #pragma unroll
                            for (int u = 0; u < 4; ++u) {
                                acc2[r][u] = ffma2(xv[i].x, wv[u][half].x, acc2[r][u]);
                                acc2[r][u] = ffma2(xv[i].y, wv[u][half].y, acc2[r][u]);
                            }
                        }
                    }
                }
            }
            #pragma unroll
            for (int r = 0; r < 8; ++r) {
                int n = ng + 4 * r;
                float4 o;
                float lo, hi;
                unpack2(acc2[r][0], lo, hi); o.x = lo + hi + bj.x;
                unpack2(acc2[r][1], lo, hi); o.y = lo + hi + bj.y;
                unpack2(acc2[r][2], lo, hi); o.z = lo + hi + bj.z;
                unpack2(acc2[r][3], lo, hi); o.w = lo + hi + bj.w;
                *(float4*)&qk[n * XS + jb] = o;
            }
        }

        // ---- prefetch gather for row rr+1 (overlaps with phase 3/4) ----
        if (rr + 1 < RPC && row + 1 < n_rows) {
            const int rown = row + 1;
            #pragma unroll
            for (int r8 = 0; r8 < 8; ++r8) {
                int n = wid * 8 + r8;
                int id = g_ids[rown * 32 + n];
                float4 v = emb4[(long)id * 32 + lane];
                *(float4*)&xnxt[n * XS + lane * 4] = v;
            }
            if (t < 32) {
                int id = g_ids[rown * 32 + t];
                float mk = g_mask[rown * 32 + t];
                float tm = g_times[rown];
                float z  = g_theta[id] - g_mu[id] * tm;
                wnxt[t] = mk / (1.0f + __expf(-z));
            }
        }
        __syncthreads();   // qk ready (and xnxt writes ordered before next row's reads)

        // ---- phase 3: scores (column m = lane), softmax via shuffles,
        //      fold pooling weights into column vector c; packed f32x2 dot ----
        if (active) {
            unsigned long long s2[8];
            #pragma unroll
            for (int i = 0; i < 8; ++i) s2[i] = 0ULL;
            const float* kp = &qk[lane * XS + 64];     // k row m = lane
            const float* qp = &qk[(wid * 8) * XS];     // q rows 8w..8w+7 (broadcast)
            #pragma unroll 2
            for (int hs = 0; hs < 16; ++hs) {
                const int h = hs * 4;
                ulonglong2 kv = *(const ulonglong2*)(kp + h);
                #pragma unroll
                for (int i = 0; i < 8; ++i) {
                    ulonglong2 qv = *(const ulonglong2*)(qp + i * XS + h);
                    s2[i] = ffma2(qv.x, kv.x, s2[i]);
                    s2[i] = ffma2(qv.y, kv.y, s2[i]);
                }
            }
            float cpart = 0.f;
            #pragma unroll
            for (int i = 0; i < 8; ++i) {
                float a, b;
                unpack2(s2[i], a, b);
                float v = (a + b) * 0.125f;            // / sqrt(H=64)
                float mx = v;
                #pragma unroll
                for (int o = 16; o > 0; o >>= 1)
                    mx = fmaxf(mx, __shfl_xor_sync(0xffffffffu, mx, o));
                float ex = __expf(v - mx);
                float sum = ex;
                #pragma unroll
                for (int o = 16; o > 0; o >>= 1)
                    sum += __shfl_xor_sync(0xffffffffu, sum, o);
                cpart = fmaf(__fdividef(wcur[wid * 8 + i], sum), ex, cpart);
            }
            cws[wid * 32 + lane] = cpart;
        }
        __syncthreads();

        if (active && t < 32)
            cs[t] = cws[t] + cws[32 + t] + cws[64 + t] + cws[96 + t];
        __syncthreads();

        // ---- phase 4: pooled[d] = sum_m c[m] * x[m][d] ----
        if (active) {
            float o = 0.f;
            #pragma unroll
            for (int m = 0; m < 32; ++m)
                o = fmaf(cs[m], xcur[m * XS + t], o);
            g_out[(long)row * 128 + t] = o;
        }
        __syncthreads();   // phase-4 reads of xcur/cs done before next row reuses them
    }
}

extern "C" void kernel_launch(void* const* d_in, const int* in_sizes, int n_in,
                              void* d_out, int out_size)
{
    (void)n_in; (void)out_size;
    const int*   g_ids   = (const int*)  d_in[0];
    const float* g_mask  = (const float*)d_in[1];
    const float* g_times = (const float*)d_in[2];
    const float* g_emb   = (const float*)d_in[3];
    const float* g_qW    = (const float*)d_in[4];
    const float* g_qb    = (const float*)d_in[5];
    const float* g_kW    = (const float*)d_in[6];
    const float* g_kb    = (const float*)d_in[7];
    const float* g_theta = (const float*)d_in[8];
    const float* g_mu    = (const float*)d_in[9];
    float* g_out = (float*)d_out;

    const int n_rows = in_sizes[2];               // B*LS = 16384
    const int smem_bytes = SMEM_FLOATS * sizeof(float);

    cudaFuncSetAttribute(concept_emb_kernel,
                         cudaFuncAttributeMaxDynamicSharedMemorySize, smem_bytes);

    const int blocks = (n_rows + RPC - 1) / RPC;  // 2048
    concept_emb_kernel<<<blocks, THREADS, smem_bytes>>>(
        g_ids, g_mask, g_times, g_emb, g_qW, g_qb, g_kW, g_kb,
        g_theta, g_mu, g_out, n_rows);
}

// round 14
// speedup vs baseline: 3.5626x; 3.5626x over previous
#include <cuda_runtime.h>

#define XS 132         // row stride in smem (floats), mult of 4, not mult of 32
#define NV_MAX 50000

// precomputed [q|k] projections per vocab entry (bias folded): [v][0..63]=q, [64..127]=k
__device__ float g_Eqk[(long)NV_MAX * 128];

// ---- packed fp32x2 helpers (sm_10x FFMA2 path, PTX-only) ----
__device__ __forceinline__ unsigned long long ffma2(unsigned long long a,
                                                    unsigned long long b,
                                                    unsigned long long c) {
    unsigned long long d;
    asm("fma.rn.f32x2 %0, %1, %2, %3;" : "=l"(d) : "l"(a), "l"(b), "l"(c));
    return d;
}
__device__ __forceinline__ void unpack2(unsigned long long v, float& lo, float& hi) {
    asm("mov.b64 {%0, %1}, %2;" : "=f"(lo), "=f"(hi) : "l"(v));
}

// ============================================================
// Kernel 1: Eqk[v] = [emb[v]@qW^T + qb | emb[v]@kW^T + kb]
// CTA = 32 contiguous vocab rows, 128 threads. (R12 phase-2 structure.)
// ============================================================
__global__ __launch_bounds__(128, 4)
void proj_kernel(const float* __restrict__ g_emb,
                 const float* __restrict__ g_qW,
                 const float* __restrict__ g_qb,
                 const float* __restrict__ g_kW,
                 const float* __restrict__ g_kb,
                 int nv)
{
    __shared__ float xs[32 * XS];
    __shared__ float bs[128];

    const int t    = threadIdx.x;
    const int lane = t & 31;
    const int wid  = t >> 5;
    const int ng = lane & 3;            // interleaved rows {ng, ng+4, ..., ng+28}
    const int jg = lane >> 2;
    const int jb = 32 * wid + 4 * jg;   // 4 consecutive output cols

    const float* Wsel = (wid < 2) ? g_qW : g_kW;
    const float* wbase = Wsel + (jb & 63) * 128;

    bs[t] = (t < 64) ? g_qb[t] : g_kb[t - 64];

    const int v0 = blockIdx.x * 32;
    const float4* emb4 = (const float4*)g_emb;
    #pragma unroll
    for (int r8 = 0; r8 < 8; ++r8) {
        int n = wid * 8 + r8;
        int v = v0 + n;
        float4 val = (v < nv) ? emb4[(long)v * 32 + lane] : make_float4(0.f,0.f,0.f,0.f);
        *(float4*)&xs[n * XS + lane * 4] = val;
    }
    __syncthreads();

    const float4 bj = *(const float4*)&bs[jb];

    unsigned long long acc2[8][4];   // [r][u]: output (row ng+4r, col jb+u)
    #pragma unroll
    for (int r = 0; r < 8; ++r)
        #pragma unroll
        for (int u = 0; u < 4; ++u) acc2[r][u] = 0ULL;

    const float* xp = &xs[ng * XS];
    #pragma unroll 1
    for (int ds = 0; ds < 32; ++ds) {
        const int d = ds * 4;
        ulonglong2 wv[4];
        #pragma unroll
        for (int u = 0; u < 4; ++u)
            wv[u] = *(const ulonglong2*)(wbase + u * 128 + d);
        #pragma unroll
        for (int rh = 0; rh < 2; ++rh) {
            ulonglong2 xv[4];
            #pragma unroll
            for (int i = 0; i < 4; ++i)
                xv[i] = *(const ulonglong2*)(xp + (4 * (rh * 4 + i)) * XS + d);
            #pragma unroll
            for (int i = 0; i < 4; ++i) {
                const int r = rh * 4 + i;
                #pragma unroll
                for (int u = 0; u < 4; ++u) {
                    acc2[r][u] = ffma2(xv[i].x, wv[u].x, acc2[r][u]);
                    acc2[r][u] = ffma2(xv[i].y, wv[u].y, acc2[r][u]);
                }
            }
        }
    }
    #pragma unroll
    for (int r = 0; r < 8; ++r) {
        int v = v0 + ng + 4 * r;
        if (v < nv) {
            float4 o;
            float lo, hi;
            unpack2(acc2[r][0], lo, hi); o.x = lo + hi + bj.x;
            unpack2(acc2[r][1], lo, hi); o.y = lo + hi + bj.y;
            unpack2(acc2[r][2], lo, hi); o.z = lo + hi + bj.z;
            unpack2(acc2[r][3], lo, hi); o.w = lo + hi + bj.w;
            *(float4*)&g_Eqk[(long)v * 128 + jb] = o;
        }
    }
}

// ============================================================
// Kernel 2: per row — gather Eqk[id], scores+softmax -> c, pool emb rows.
// One row per CTA, 128 threads, ~18 KB smem -> 8 CTAs/SM.
// ============================================================
__global__ __launch_bounds__(128, 8)
void attn_pool_kernel(const int*   __restrict__ g_ids,
                      const float* __restrict__ g_mask,
                      const float* __restrict__ g_times,
                      const float* __restrict__ g_emb,
                      const float* __restrict__ g_theta,
                      const float* __restrict__ g_mu,
                      float*       __restrict__ g_out)
{
    __shared__ float qk[32 * XS];   // [n][0..63]=q, [64..127]=k
    __shared__ float wrow[32];      // sx * mask
    __shared__ float cws[128];
    __shared__ float cs[32];
    __shared__ int   ids[32];

    const int row  = blockIdx.x;
    const int t    = threadIdx.x;
    const int lane = t & 31;
    const int wid  = t >> 5;

    // ---- gather qk rows from Eqk (L2-resident) ----
    const float4* E4 = (const float4*)g_Eqk;
    #pragma unroll
    for (int r8 = 0; r8 < 8; ++r8) {
        int n = wid * 8 + r8;
        int id = g_ids[row * 32 + n];            // warp-uniform broadcast LDG
        float4 v = E4[(long)id * 32 + lane];
        *(float4*)&qk[n * XS + lane * 4] = v;
    }
    if (t < 32) {
        int id = g_ids[row * 32 + t];
        ids[t] = id;
        float mk = g_mask[row * 32 + t];
        float tm = g_times[row];
        float z  = g_theta[id] - g_mu[id] * tm;
        wrow[t] = mk / (1.0f + __expf(-z));
    }
    __syncthreads();

    // ---- scores (column m = lane), softmax via shuffles, fold weights -> c ----
    {
        unsigned long long s2[8];
        #pragma unroll
        for (int i = 0; i < 8; ++i) s2[i] = 0ULL;
        const float* kp = &qk[lane * XS + 64];     // k row m = lane
        const float* qp = &qk[(wid * 8) * XS];     // q rows 8w..8w+7 (broadcast)
        #pragma unroll 2
        for (int hs = 0; hs < 16; ++hs) {
            const int h = hs * 4;
            ulonglong2 kv = *(const ulonglong2*)(kp + h);
            #pragma unroll
            for (int i = 0; i < 8; ++i) {
                ulonglong2 qv = *(const ulonglong2*)(qp + i * XS + h);
                s2[i] = ffma2(qv.x, kv.x, s2[i]);
                s2[i] = ffma2(qv.y, kv.y, s2[i]);
            }
        }
        float cpart = 0.f;
        #pragma unroll
        for (int i = 0; i < 8; ++i) {
            float a, b;
            unpack2(s2[i], a, b);
            float v = (a + b) * 0.125f;            // / sqrt(H=64)
            float mx = v;
            #pragma unroll
            for (int o = 16; o > 0; o >>= 1)
                mx = fmaxf(mx, __shfl_xor_sync(0xffffffffu, mx, o));
            float ex = __expf(v - mx);
            float sum = ex;
            #pragma unroll
            for (int o = 16; o > 0; o >>= 1)
                sum += __shfl_xor_sync(0xffffffffu, sum, o);
            cpart = fmaf(__fdividef(wrow[wid * 8 + i], sum), ex, cpart);
        }
        cws[wid * 32 + lane] = cpart;
    }
    __syncthreads();

    if (t < 32)
        cs[t] = cws[t] + cws[32 + t] + cws[64 + t] + cws[96 + t];
    __syncthreads();

    // ---- pooled[d] = sum_m c[m] * emb[id_m][d]  (coalesced 128B per warp, L2-hit) ----
    {
        float o = 0.f;
        #pragma unroll
        for (int m = 0; m < 32; ++m)
            o = fmaf(cs[m], g_emb[(long)ids[m] * 128 + t], o);
        g_out[(long)row * 128 + t] = o;
    }
}

extern "C" void kernel_launch(void* const* d_in, const int* in_sizes, int n_in,
                              void* d_out, int out_size)
{
    (void)n_in; (void)out_size;
    const int*   g_ids   = (const int*)  d_in[0];
    const float* g_mask  = (const float*)d_in[1];
    const float* g_times = (const float*)d_in[2];
    const float* g_emb   = (const float*)d_in[3];
    const float* g_qW    = (const float*)d_in[4];
    const float* g_qb    = (const float*)d_in[5];
    const float* g_kW    = (const float*)d_in[6];
    const float* g_kb    = (const float*)d_in[7];
    const float* g_theta = (const float*)d_in[8];
    const float* g_mu    = (const float*)d_in[9];
    float* g_out = (float*)d_out;

    const int n_rows = in_sizes[2];               // B*LS = 16384
    int nv = in_sizes[3] / 128;                   // vocab size (50000)
    if (nv > NV_MAX) nv = NV_MAX;

    proj_kernel<<<(nv + 31) / 32, 128>>>(g_emb, g_qW, g_qb, g_kW, g_kb, nv);
    attn_pool_kernel<<<n_rows, 128>>>(g_ids, g_mask, g_times, g_emb,
                                      g_theta, g_mu, g_out);
}